// round 10
// baseline (speedup 1.0000x reference)
#include <cuda_runtime.h>
#include <cstdint>

#define NQ 4096
#define TPB 256

// Swizzle: s(e) = e ^ ((e>>5 & 7)<<2) ^ ((e>>8 & 1)<<4).
// Bank bits of s(e): {e0, e1, e2^e5, e3^e6, e4^e7^e8}.
// Bijective on [0,4096); XORs only into bits 2-4 -> float4 alignment kept.
__device__ __forceinline__ int s_idx(int e) {
    return e ^ (((e >> 5) & 7) << 2) ^ (((e >> 8) & 1) << 4);
}

__device__ __forceinline__ void butterfly16(float v[16]) {
#pragma unroll
    for (int bs = 1; bs < 16; bs <<= 1) {
#pragma unroll
        for (int i = 0; i < 16; i++) {
            if ((i & bs) == 0) {
                float a = v[i], b = v[i + bs];
                v[i] = a + b;
                v[i + bs] = a - b;
            }
        }
    }
}

// Radix-16^3 FWHT over one row held in bufA (SWIZZLED layout), with v[]
// preloaded with P1 values (regs = dims 8-11). Does STS->bar->P2->bar->P3->STG.
// Caller must have applied scale during the P1 load.
__device__ __forceinline__ void fwht_core(float v[16], float* bufA, float* yr,
                                          int t) {
    butterfly16(v);  // dims 8-11

    // STS: e = r*256 + t (lanes vary e0-4 -> CF)
#pragma unroll
    for (int r = 0; r < 16; r++)
        bufA[s_idx(r * 256 + t)] = v[r];
    __syncthreads();

    // P2: regs = dims 0-3; float4 at e = 16t+4q (chunk bits distinct -> CF)
#pragma unroll
    for (int q = 0; q < 4; q++) {
        float4 f = *reinterpret_cast<const float4*>(bufA + s_idx((t << 4) | (q << 2)));
        v[4 * q + 0] = f.x;
        v[4 * q + 1] = f.y;
        v[4 * q + 2] = f.z;
        v[4 * q + 3] = f.w;
    }
    butterfly16(v);  // dims 0-3
#pragma unroll
    for (int q = 0; q < 4; q++) {
        *reinterpret_cast<float4*>(bufA + s_idx((t << 4) | (q << 2))) =
            make_float4(v[4 * q], v[4 * q + 1], v[4 * q + 2], v[4 * q + 3]);
    }
    __syncthreads();

    // P3: regs = dims 4-7; e = (t&15) | (i<<4) | ((t>>4)<<8) (banks bijective -> CF)
    const int ebase = (t & 15) | ((t >> 4) << 8);
#pragma unroll
    for (int i = 0; i < 16; i++)
        v[i] = bufA[s_idx(ebase | (i << 4))];
    butterfly16(v);  // dims 4-7

    // STG: 16 x STG.32, each covering 2 full 64B segments across the warp
#pragma unroll
    for (int i = 0; i < 16; i++)
        yr[ebase | (i << 4)] = v[i];
}

// Two FWHT rows per CTA. Row B's 16KB is prefetched into bufB via a plain
// cp.async.bulk at CTA start, fully overlapped with row A's LDG+compute+STG.
// Row B then starts from SMEM (CF linear reads) instead of waiting on DRAM.
__global__ void __launch_bounds__(TPB) fwht4096x2_kernel(const float* __restrict__ x,
                                                         float* __restrict__ y) {
    __shared__ float bufA[NQ];              // exchange buffer (swizzled layout)
    __shared__ alignas(16) float bufB[NQ];  // row-B prefetch (LINEAR layout)
    __shared__ alignas(8) uint64_t mbar;

    const int t = threadIdx.x;
    const size_t baseA = (size_t)(2 * blockIdx.x) * NQ;
    const size_t baseB = baseA + NQ;
    const float scale = 0.015625f;  // 1/sqrt(4096)
    float v[16];

    uint32_t mb, sbB;
    asm("{ .reg .u64 a; cvta.to.shared.u64 a, %1; cvt.u32.u64 %0, a; }"
        : "=r"(mb) : "l"(&mbar));
    asm("{ .reg .u64 a; cvta.to.shared.u64 a, %1; cvt.u32.u64 %0, a; }"
        : "=r"(sbB) : "l"(bufB));

    // ---- mbarrier init, visible to async proxy, then everyone past it ----
    if (t == 0) {
        asm volatile("mbarrier.init.shared.b64 [%0], 1;" :: "r"(mb) : "memory");
        asm volatile("fence.proxy.async.shared::cta;" ::: "memory");
    }
    __syncthreads();

    // ---- Kick off row-B prefetch (async, no registers, no tensormap) ----
    if (t == 0) {
        asm volatile("mbarrier.arrive.expect_tx.shared.b64 _, [%0], %1;"
                     :: "r"(mb), "r"(NQ * 4) : "memory");
        asm volatile(
            "cp.async.bulk.shared::cluster.global.mbarrier::complete_tx::bytes "
            "[%0], [%1], %2, [%3];"
            :: "r"(sbB), "l"(x + baseB), "r"(NQ * 4), "r"(mb)
            : "memory");
    }

    // ================= Row A: direct-from-gmem P1 =================
    {
        const float* xr = x + baseA + t;
#pragma unroll
        for (int r = 0; r < 16; r++)
            v[r] = xr[r * 256] * scale;  // 16 coalesced LDG.32
        fwht_core(v, bufA, y + baseA, t);
    }

    // ================= Row B: P1 from prefetched SMEM =================
    // Wait for the bulk copy (long since complete in steady state).
    asm volatile(
        "{\n\t.reg .pred P;\n"
        "W_%=:\n\t"
        "mbarrier.try_wait.parity.shared::cta.b64 P, [%0], 0;\n\t"
        "@!P bra W_%=;\n\t}"
        :: "r"(mb) : "memory");

    // bufB is linear: e = r*256 + t -> bank t%32, conflict-free.
#pragma unroll
    for (int r = 0; r < 16; r++)
        v[r] = bufB[r * 256 + t] * scale;

    // All warps must be done with row A's P3 reads of bufA before reuse.
    __syncthreads();

    fwht_core(v, bufA, y + baseB, t);
}

extern "C" void kernel_launch(void* const* d_in, const int* in_sizes, int n_in,
                              void* d_out, int out_size) {
    const float* x = (const float*)d_in[0];
    float* y = (float*)d_out;
    const int rows = in_sizes[0] / NQ;  // 8192 rows (even)
    fwht4096x2_kernel<<<rows / 2, TPB>>>(x, y);
}